// round 9
// baseline (speedup 1.0000x reference)
#include <cuda_runtime.h>
#include <cstdint>

// celerite GP factor + solve + loglike. N=262144, J=16, R=4.
// Chunked-parallel scans with OV warm-up (contracting recurrences).
// Forward: warm/main/peel phase split (no per-iter predicates), smem W-row
// broadcast. Backward: distance-2 prefetch on ALL streams.

#define JDIM 16
#define RDIM 4
#define OV   12
#define NMAX 262144
#define MAXC 8192

__device__ float g_W[(size_t)NMAX * JDIM];     // 16 MB scratch: W rows
__device__ float g_z[(size_t)NMAX * RDIM];     // 4 MB scratch: z rows (/d)
__device__ float g_logd[MAXC];                 // per-chunk sum(log d)
__device__ float g_yx[MAXC * RDIM];            // per-chunk sum(y*x) per RHS

__device__ __forceinline__ float fast_rcp(float x) {
    float r;
    asm("rcp.approx.f32 %0, %1;" : "=f"(r) : "f"(x));
    r = r * (2.0f - x * r);
    return r;
}

// One forward step. DO_STORE / DO_PREFETCH are compile-time literals at each
// expansion, so dead paths fold away.
#define FWD_STEP(DO_STORE, DO_PREFETCH)                                      \
{                                                                            \
    float pjk0=npj0.x, pjk1=npj0.y, pjk2=npj0.z, pjk3=npj0.w;                \
    float pjk4=npj1.x, pjk5=npj1.y, pjk6=npj1.z, pjk7=npj1.w;                \
    float ujk0=nuj0.x, ujk1=nuj0.y, ujk2=nuj0.z, ujk3=nuj0.w;                \
    float ujk4=nuj1.x, ujk5=nuj1.y, ujk6=nuj1.z, ujk7=nuj1.w;                \
    float pi = npi, ui = nui, vi = nvi, an = nan;                            \
    float2 y2 = ny2;                                                         \
    if (DO_PREFETCH) {                                                       \
        pP8 += JDIM; pPi += JDIM; pU8 += JDIM; pUi += JDIM; pVi += JDIM;     \
        pa1 += 1; py2 += RDIM;                                               \
        npj0 = *(const float4*)(pP8);                                        \
        npj1 = *(const float4*)(pP8 + 4);                                    \
        npi  = *pPi;                                                         \
        nuj0 = *(const float4*)(pU8);                                        \
        nuj1 = *(const float4*)(pU8 + 4);                                    \
        nui  = *pUi;                                                         \
        nvi  = *pVi;                                                         \
        nan  = *pa1;                                                         \
        ny2  = *(const float2*)(py2);                                        \
    }                                                                        \
    f0 = pi * (f0 + wprev * zp0);                                            \
    f1 = pi * (f1 + wprev * zp1);                                            \
    s8[0] *= pi * pjk0; s8[1] *= pi * pjk1;                                  \
    s8[2] *= pi * pjk2; s8[3] *= pi * pjk3;                                  \
    s8[4] *= pi * pjk4; s8[5] *= pi * pjk5;                                  \
    s8[6] *= pi * pjk6; s8[7] *= pi * pjk7;                                  \
    float t01 = fmaf(s8[1], ujk1, s8[0] * ujk0);                             \
    float t23 = fmaf(s8[3], ujk3, s8[2] * ujk2);                             \
    float t45 = fmaf(s8[5], ujk5, s8[4] * ujk4);                             \
    float t67 = fmaf(s8[7], ujk7, s8[6] * ujk6);                             \
    float su = (t01 + t23) + (t45 + t67);                                    \
    su += __shfl_xor_sync(FULL, su, 16);                                     \
    float tD = ui * su;                                                      \
    float t0 = ui * f0, t1 = ui * f1;                                        \
    tD += __shfl_xor_sync(FULL, tD, 1);                                      \
    t0 += __shfl_xor_sync(FULL, t0, 1); t1 += __shfl_xor_sync(FULL, t1, 1);  \
    tD += __shfl_xor_sync(FULL, tD, 2);                                      \
    t0 += __shfl_xor_sync(FULL, t0, 2); t1 += __shfl_xor_sync(FULL, t1, 2);  \
    tD += __shfl_xor_sync(FULL, tD, 4);                                      \
    t0 += __shfl_xor_sync(FULL, t0, 4); t1 += __shfl_xor_sync(FULL, t1, 4);  \
    tD += __shfl_xor_sync(FULL, tD, 8);                                      \
    t0 += __shfl_xor_sync(FULL, t0, 8); t1 += __shfl_xor_sync(FULL, t1, 8);  \
    float dn = an - tD;                                                      \
    float rd = fast_rcp(dn);                                                 \
    float wi = (vi - su) * rd;                                               \
    float zn0 = y2.x - t0;                                                   \
    float zn1 = y2.y - t1;                                                   \
    if (DO_STORE) {                                                          \
        if (h == 0) *pgW = wi;                                               \
        if (i == 0) *(float2*)pgz = make_float2(zn0 * rd, zn1 * rd);         \
        pgW += JDIM; pgz += RDIM;                                            \
        llogd += __logf(dn);                                                 \
    }                                                                        \
    sWb[i] = wi;  /* lanes (i,0),(i,1) write identical wi: benign */         \
    __syncwarp();                                                            \
    float4 wa  = *(const float4*)(sWb + 8 * h);                              \
    float4 wbv = *(const float4*)(sWb + 8 * h + 4);                          \
    sWb = (float*)((uintptr_t)sWb ^ 64u);  /* double-buffer toggle */        \
    float dw = dn * wi;                                                      \
    s8[0] = fmaf(dw, wa.x,  s8[0]); s8[1] = fmaf(dw, wa.y,  s8[1]);          \
    s8[2] = fmaf(dw, wa.z,  s8[2]); s8[3] = fmaf(dw, wa.w,  s8[3]);          \
    s8[4] = fmaf(dw, wbv.x, s8[4]); s8[5] = fmaf(dw, wbv.y, s8[5]);          \
    s8[6] = fmaf(dw, wbv.z, s8[6]); s8[7] = fmaf(dw, wbv.w, s8[7]);          \
    wprev = wi; zp0 = zn0; zp1 = zn1;                                        \
}

// ---------------------------------------------------------------------------
// Kernel 1: fused factorization + forward solve. One warp per chunk.
// Lane layout: i = lane&15, h = lane>>4; lane holds S[i][8h..8h+8),
// F[i][2h..2h+2). Prefetch distance 1; warm/main/peel structure.
// ---------------------------------------------------------------------------
__global__ void __launch_bounds__(256, 3)
factor_forward_kernel(const float* __restrict__ a, const float* __restrict__ U,
                      const float* __restrict__ V, const float* __restrict__ P,
                      const float* __restrict__ y, int N, int C, int L)
{
    __shared__ __align__(128) float sWarr[8][32];   // per-warp 2x16 floats

    int warp = (blockIdx.x * blockDim.x + threadIdx.x) >> 5;
    if (warp >= C) return;
    int lane = threadIdx.x & 31;
    int i = lane & 15;
    int h = lane >> 4;
    int s = warp * L;
    if (s >= N) return;
    int e = min(s + L, N);
    int m0 = max(0, s - OV);

    const unsigned FULL = 0xffffffffu;
    float* sWb = &sWarr[(threadIdx.x >> 5)][0];

    // ---- init at n = m0 (exact for chunk 0; decayed-approx otherwise)
    float s8[8];
    {
        float an = a[m0];
        float vi = V[(size_t)m0 * JDIM + i];
        float rd = fast_rcp(an);
        float wi = vi * rd;
        float wj[8];
#pragma unroll
        for (int k = 0; k < 8; k++) wj[k] = __shfl_sync(FULL, wi, 8 * h + k);
        float dw = an * wi;
#pragma unroll
        for (int k = 0; k < 8; k++) s8[k] = dw * wj[k];

        if (m0 == s) {   // chunk 0: store row 0
            if (h == 0) g_W[(size_t)m0 * JDIM + i] = wi;
            float2 y0 = *(const float2*)(y + (size_t)m0 * RDIM + 2 * h);
            if (i == 0) *(float2*)(g_z + (size_t)m0 * RDIM + 2 * h) =
                            make_float2(y0.x * rd, y0.y * rd);
        }
    }
    float2 ym = *(const float2*)(y + (size_t)m0 * RDIM + 2 * h);
    float zp0 = ym.x, zp1 = ym.y;
    float f0 = 0.f, f1 = 0.f;
    float wprev;   // W row m0
    {
        float vi = V[(size_t)m0 * JDIM + i];
        wprev = vi * fast_rcp(a[m0]);
    }
    float llogd = (m0 == s) ? __logf(a[m0]) : 0.f;

    if (m0 + 1 >= e) { if (lane == 0) g_logd[warp] = llogd; return; }

    // ---- load pointers at row m0+1 (P uses row n-1)
    const float* pP8 = P + (size_t)m0 * JDIM + 8 * h;
    const float* pPi = P + (size_t)m0 * JDIM + i;
    const float* pU8 = U + (size_t)(m0 + 1) * JDIM + 8 * h;
    const float* pUi = U + (size_t)(m0 + 1) * JDIM + i;
    const float* pVi = V + (size_t)(m0 + 1) * JDIM + i;
    const float* pa1 = a + (m0 + 1);
    const float* py2 = y + (size_t)(m0 + 1) * RDIM + 2 * h;

    int sm = (m0 + 1 > s) ? (m0 + 1) : s;   // first stored row
    float* pgW = g_W + (size_t)sm * JDIM + i;
    float* pgz = g_z + (size_t)sm * RDIM + 2 * h;

    // preload row m0+1
    float4 npj0 = *(const float4*)(pP8);
    float4 npj1 = *(const float4*)(pP8 + 4);
    float  npi  = *pPi;
    float4 nuj0 = *(const float4*)(pU8);
    float4 nuj1 = *(const float4*)(pU8 + 4);
    float  nui  = *pUi;
    float  nvi  = *pVi;
    float  nan  = *pa1;
    float2 ny2  = *(const float2*)(py2);

    // ---- warm phase: rows [m0+1, s) — no stores/log (empty for chunk 0)
#pragma unroll 1
    for (int n = m0 + 1; n < s; n++) FWD_STEP(false, true)

    // ---- main phase: rows [sm, e-1)
#pragma unroll 1
    for (int n = sm; n < e - 1; n++) FWD_STEP(true, true)

    // ---- peeled last row e-1: no prefetch (keeps loads in-bounds)
    FWD_STEP(true, false)

    if (lane == 0) g_logd[warp] = llogd;
}

// ---------------------------------------------------------------------------
// Kernel 2: backward solve, reverse chunked with warm-up. Distance-2
// prefetch on ALL streams (G: P[n],U[n+1],z[n+1]; body: W[n],z[n],y[n]).
// ---------------------------------------------------------------------------
__global__ void __launch_bounds__(256, 4)
backward_kernel(const float* __restrict__ U, const float* __restrict__ P,
                const float* __restrict__ y, float* __restrict__ xout,
                int N, int C, int L)
{
    int warp = (blockIdx.x * blockDim.x + threadIdx.x) >> 5;
    if (warp >= C) return;
    int lane = threadIdx.x & 31;
    int i = lane & 15;
    int h = lane >> 4;
    int s = warp * L;
    if (s >= N) return;
    int e = min(s + L, N);

    const unsigned FULL = 0xffffffffu;

    float g0 = 0.f, g1 = 0.f;
    float acc0 = 0.f, acc1 = 0.f;

    if (e == N) {   // last chunk: x[N-1] = z[N-1]
        float2 z2 = *(const float2*)(g_z + (size_t)(N - 1) * RDIM + 2 * h);
        float2 yv = *(const float2*)(y + (size_t)(N - 1) * RDIM + 2 * h);
        if (i == 0) *(float2*)(xout + (size_t)(N - 1) * RDIM + 2 * h) = z2;
        acc0 = yv.x * z2.x;
        acc1 = yv.y * z2.y;
    }

    int n_start = min(e - 1 + OV, N - 2);
    if (n_start < s) {
        if (i == 0) { g_yx[warp*RDIM+2*h] = acc0; g_yx[warp*RDIM+2*h+1] = acc1; }
        return;
    }

    // distance-2 buffers: A = row n, B = row n-1 (clamped)
    float piA, u1A, wiA; float2 z1A, znA, yvA;
    float piB, u1B, wiB; float2 z1B, znB, yvB;
    {
        int rA = n_start;
        piA = P[(size_t)rA * JDIM + i];
        u1A = U[(size_t)(rA + 1) * JDIM + i];
        z1A = *(const float2*)(g_z + (size_t)(rA + 1) * RDIM + 2 * h);
        wiA = g_W[(size_t)rA * JDIM + i];
        znA = *(const float2*)(g_z + (size_t)rA * RDIM + 2 * h);
        yvA = *(const float2*)(y + (size_t)rA * RDIM + 2 * h);
        int rB = (n_start - 1 > s) ? n_start - 1 : s;
        piB = P[(size_t)rB * JDIM + i];
        u1B = U[(size_t)(rB + 1) * JDIM + i];
        z1B = *(const float2*)(g_z + (size_t)(rB + 1) * RDIM + 2 * h);
        wiB = g_W[(size_t)rB * JDIM + i];
        znB = *(const float2*)(g_z + (size_t)rB * RDIM + 2 * h);
        yvB = *(const float2*)(y + (size_t)rB * RDIM + 2 * h);
    }

    int pn = (n_start - 2 > s) ? n_start - 2 : s;
    const float* pPp = P + (size_t)pn * JDIM + i;
    const float* pUp = U + (size_t)(pn + 1) * JDIM + i;
    const float* pzp = g_z + (size_t)(pn + 1) * RDIM + 2 * h;
    const float* pWp = g_W + (size_t)pn * JDIM + i;
    const float* pzb = g_z + (size_t)pn * RDIM + 2 * h;
    const float* pyp = y + (size_t)pn * RDIM + 2 * h;

#pragma unroll 1
    for (int n = n_start; n >= s; n--) {
        float pi = piA, u1 = u1A, wi = wiA;
        float2 z1 = z1A, zn = znA, yv = yvA;
        // rotate B -> A, load new B (row pn)
        piA = piB; u1A = u1B; z1A = z1B; wiA = wiB; znA = znB; yvA = yvB;
        piB = *pPp; u1B = *pUp; z1B = *(const float2*)pzp;
        wiB = *pWp; znB = *(const float2*)pzb; yvB = *(const float2*)pyp;
        int dec = (pn > s) ? JDIM : 0;
        pn -= (dec >> 4);
        pPp -= dec; pUp -= dec; pWp -= dec;
        pzp -= (dec >> 2); pzb -= (dec >> 2); pyp -= (dec >> 2);

        g0 = pi * (g0 + u1 * z1.x);
        g1 = pi * (g1 + u1 * z1.y);
        if (n < e) {   // warp-uniform branch
            float t0 = wi * g0, t1 = wi * g1;
            t0 += __shfl_xor_sync(FULL, t0, 1);  t1 += __shfl_xor_sync(FULL, t1, 1);
            t0 += __shfl_xor_sync(FULL, t0, 2);  t1 += __shfl_xor_sync(FULL, t1, 2);
            t0 += __shfl_xor_sync(FULL, t0, 4);  t1 += __shfl_xor_sync(FULL, t1, 4);
            t0 += __shfl_xor_sync(FULL, t0, 8);  t1 += __shfl_xor_sync(FULL, t1, 8);
            float x0 = zn.x - t0;
            float x1 = zn.y - t1;
            if (i == 0) *(float2*)(xout + (size_t)n * RDIM + 2 * h) =
                            make_float2(x0, x1);
            acc0 = fmaf(yv.x, x0, acc0);
            acc1 = fmaf(yv.y, x1, acc1);
        }
    }

    if (i == 0) {
        g_yx[warp * RDIM + 2 * h + 0] = acc0;
        g_yx[warp * RDIM + 2 * h + 1] = acc1;
    }
}

// ---------------------------------------------------------------------------
// Kernel 3: finalize loglike. 4 warps, warp r owns RHS r; lanes stride over
// chunks, fp64 butterfly. Fixed order -> deterministic.
// ---------------------------------------------------------------------------
__global__ void finalize_kernel(float* __restrict__ out, int N, int Cf, int Cb)
{
    const unsigned FULL = 0xffffffffu;
    int wq = threadIdx.x >> 5;
    int lane = threadIdx.x & 31;

    double sl = 0.0;
    for (int c = lane; c < Cf; c += 32) sl += (double)g_logd[c];
#pragma unroll
    for (int o = 16; o > 0; o >>= 1) sl += __shfl_xor_sync(FULL, sl, o);
    double norm = -0.5 * (sl + (double)N * log(6.283185307179586));

    double syx = 0.0;
    for (int c = lane; c < Cb; c += 32) syx += (double)g_yx[c * RDIM + wq];
#pragma unroll
    for (int o = 16; o > 0; o >>= 1) syx += __shfl_xor_sync(FULL, syx, o);

    if (lane == 0 && wq < RDIM)
        out[(size_t)N * RDIM + wq] = (float)(norm - 0.5 * syx);
}

// ---------------------------------------------------------------------------
extern "C" void kernel_launch(void* const* d_in, const int* in_sizes, int n_in,
                              void* d_out, int out_size)
{
    const float* a = (const float*)d_in[0];
    const float* U = (const float*)d_in[1];
    const float* V = (const float*)d_in[2];
    const float* P = (const float*)d_in[3];
    const float* y = (const float*)d_in[4];
    float* out = (float*)d_out;

    int N = in_sizes[0];

    // forward: 148 SMs x 24 warps = 3552 chunks
    int tf = 3552;
    int Lf = (N + tf - 1) / tf; if (Lf < 1) Lf = 1;
    int Cf = (N + Lf - 1) / Lf;
    if (Cf > MAXC) { Lf = (N + MAXC - 1) / MAXC; Cf = (N + Lf - 1) / Lf; }

    // backward: 148 SMs x 32 warps = 4736 chunks
    int tb = 4736;
    int Lb = (N + tb - 1) / tb; if (Lb < 1) Lb = 1;
    int Cb = (N + Lb - 1) / Lb;
    if (Cb > MAXC) { Lb = (N + MAXC - 1) / MAXC; Cb = (N + Lb - 1) / Lb; }

    int threads = 256;
    int blocksF = (Cf * 32 + threads - 1) / threads;
    int blocksB = (Cb * 32 + threads - 1) / threads;

    factor_forward_kernel<<<blocksF, threads>>>(a, U, V, P, y, N, Cf, Lf);
    backward_kernel<<<blocksB, threads>>>(U, P, y, out, N, Cb, Lb);
    finalize_kernel<<<1, 128>>>(out, N, Cf, Cb);
}

// round 10
// speedup vs baseline: 1.0328x; 1.0328x over previous
#include <cuda_runtime.h>
#include <cstdint>

// celerite GP factor + solve + loglike. N=262144, J=16, R=4.
// Chunked-parallel scans with OV warm-up (contracting recurrences).
// Forward: warm/main/peel split, SHFL W-broadcast, packed f32x2 math.
// Backward: distance-2 prefetch on all streams.

#define JDIM 16
#define RDIM 4
#define OV   10
#define NMAX 262144
#define MAXC 8192

typedef unsigned long long u64t;

__device__ float g_W[(size_t)NMAX * JDIM];
__device__ float g_z[(size_t)NMAX * RDIM];
__device__ float g_logd[MAXC];
__device__ float g_yx[MAXC * RDIM];

__device__ __forceinline__ float fast_rcp(float x) {
    float r;
    asm("rcp.approx.f32 %0, %1;" : "=f"(r) : "f"(x));
    r = r * (2.0f - x * r);
    return r;
}
__device__ __forceinline__ u64t pk2(float lo, float hi) {
    u64t r; asm("mov.b64 %0, {%1,%2};" : "=l"(r) : "f"(lo), "f"(hi)); return r;
}
__device__ __forceinline__ void upk2(u64t v, float& lo, float& hi) {
    asm("mov.b64 {%0,%1}, %2;" : "=f"(lo), "=f"(hi) : "l"(v));
}
__device__ __forceinline__ u64t mul2(u64t a, u64t b) {
    u64t r; asm("mul.rn.f32x2 %0, %1, %2;" : "=l"(r) : "l"(a), "l"(b)); return r;
}
__device__ __forceinline__ u64t add2(u64t a, u64t b) {
    u64t r; asm("add.rn.f32x2 %0, %1, %2;" : "=l"(r) : "l"(a), "l"(b)); return r;
}
__device__ __forceinline__ u64t fma2(u64t a, u64t b, u64t c) {
    u64t r; asm("fma.rn.f32x2 %0, %1, %2, %3;" : "=l"(r) : "l"(a), "l"(b), "l"(c)); return r;
}

// One forward step. DO_STORE/DO_PREFETCH are literals at expansion.
#define FWD_STEP(DO_STORE, DO_PREFETCH)                                      \
{                                                                            \
    u64t pj0 = npj.x, pj1 = npj.y, pj2 = npjB.x, pj3 = npjB.y;               \
    u64t uj0 = nuj.x, uj1 = nuj.y, uj2 = nujB.x, uj3 = nujB.y;               \
    float pi = npi, ui = nui, vi = nvi, an = nan;                            \
    float2 y2 = ny2;                                                         \
    if (DO_PREFETCH) {                                                       \
        pP8 += JDIM; pPi += JDIM; pU8 += JDIM; pUi += JDIM; pVi += JDIM;     \
        pa1 += 1; py2 += RDIM;                                               \
        npj  = *(const ulonglong2*)(pP8);                                    \
        npjB = *(const ulonglong2*)(pP8 + 4);                                \
        npi  = *pPi;                                                         \
        nuj  = *(const ulonglong2*)(pU8);                                    \
        nujB = *(const ulonglong2*)(pU8 + 4);                                \
        nui  = *pUi;                                                         \
        nvi  = *pVi;                                                         \
        nan  = *pa1;                                                         \
        ny2  = *(const float2*)(py2);                                        \
    }                                                                        \
    u64t pis = pk2(pi, pi);                                                  \
    /* F recurrence (packed) */                                              \
    fP = mul2(pis, fma2(wprevP, zpP, fP));                                   \
    /* S decay (packed) */                                                   \
    s8p[0] = mul2(s8p[0], mul2(pis, pj0));                                   \
    s8p[1] = mul2(s8p[1], mul2(pis, pj1));                                   \
    s8p[2] = mul2(s8p[2], mul2(pis, pj2));                                   \
    s8p[3] = mul2(s8p[3], mul2(pis, pj3));                                   \
    /* row-dot su (packed tree) */                                           \
    u64t q0 = mul2(s8p[0], uj0), q1 = mul2(s8p[1], uj1);                     \
    u64t q2 = mul2(s8p[2], uj2), q3 = mul2(s8p[3], uj3);                     \
    u64t qt = add2(add2(q0, q1), add2(q2, q3));                              \
    float qlo, qhi; upk2(qt, qlo, qhi);                                      \
    float su = qlo + qhi;                                                    \
    su += __shfl_xor_sync(FULL, su, 16);                                     \
    float fl0, fl1; upk2(fP, fl0, fl1);                                      \
    float tD = ui * su;                                                      \
    float t0 = ui * fl0, t1 = ui * fl1;                                      \
    tD += __shfl_xor_sync(FULL, tD, 1);                                      \
    t0 += __shfl_xor_sync(FULL, t0, 1); t1 += __shfl_xor_sync(FULL, t1, 1);  \
    tD += __shfl_xor_sync(FULL, tD, 2);                                      \
    t0 += __shfl_xor_sync(FULL, t0, 2); t1 += __shfl_xor_sync(FULL, t1, 2);  \
    tD += __shfl_xor_sync(FULL, tD, 4);                                      \
    t0 += __shfl_xor_sync(FULL, t0, 4); t1 += __shfl_xor_sync(FULL, t1, 4);  \
    tD += __shfl_xor_sync(FULL, tD, 8);                                      \
    t0 += __shfl_xor_sync(FULL, t0, 8); t1 += __shfl_xor_sync(FULL, t1, 8);  \
    float dn = an - tD;                                                      \
    float rd = fast_rcp(dn);                                                 \
    float wi = (vi - su) * rd;                                               \
    float zn0 = y2.x - t0;                                                   \
    float zn1 = y2.y - t1;                                                   \
    if (DO_STORE) {                                                          \
        if (h == 0) *pgW = wi;                                               \
        if (i == 0) *(float2*)pgz = make_float2(zn0 * rd, zn1 * rd);         \
        pgW += JDIM; pgz += RDIM;                                            \
        llogd += __logf(dn);                                                 \
    }                                                                        \
    /* W-row broadcast via shfl, rank-1 update (packed) */                   \
    float w0 = __shfl_sync(FULL, wi, 8 * h + 0);                             \
    float w1 = __shfl_sync(FULL, wi, 8 * h + 1);                             \
    float w2 = __shfl_sync(FULL, wi, 8 * h + 2);                             \
    float w3 = __shfl_sync(FULL, wi, 8 * h + 3);                             \
    float w4 = __shfl_sync(FULL, wi, 8 * h + 4);                             \
    float w5 = __shfl_sync(FULL, wi, 8 * h + 5);                             \
    float w6 = __shfl_sync(FULL, wi, 8 * h + 6);                             \
    float w7 = __shfl_sync(FULL, wi, 8 * h + 7);                             \
    float dw = dn * wi;                                                      \
    u64t dwP = pk2(dw, dw);                                                  \
    s8p[0] = fma2(dwP, pk2(w0, w1), s8p[0]);                                 \
    s8p[1] = fma2(dwP, pk2(w2, w3), s8p[1]);                                 \
    s8p[2] = fma2(dwP, pk2(w4, w5), s8p[2]);                                 \
    s8p[3] = fma2(dwP, pk2(w6, w7), s8p[3]);                                 \
    wprevP = pk2(wi, wi);                                                    \
    zpP = pk2(zn0, zn1);                                                     \
}

// ---------------------------------------------------------------------------
// Kernel 1: fused factorization + forward solve. One warp per chunk.
// Lane (i = lane&15, h = lane>>4) holds S[i][8h..8h+8) (4 packed regs) and
// F[i][2h..2h+2) (1 packed reg).
// ---------------------------------------------------------------------------
__global__ void __launch_bounds__(256, 3)
factor_forward_kernel(const float* __restrict__ a, const float* __restrict__ U,
                      const float* __restrict__ V, const float* __restrict__ P,
                      const float* __restrict__ y, int N, int C, int L)
{
    int warp = (blockIdx.x * blockDim.x + threadIdx.x) >> 5;
    if (warp >= C) return;
    int lane = threadIdx.x & 31;
    int i = lane & 15;
    int h = lane >> 4;
    int s = warp * L;
    if (s >= N) return;
    int e = min(s + L, N);
    int m0 = max(0, s - OV);

    const unsigned FULL = 0xffffffffu;

    // ---- init at n = m0 (exact for chunk 0; decayed-approx otherwise)
    u64t s8p[4];
    u64t wprevP, zpP, fP;
    float llogd;
    {
        float an = a[m0];
        float vi = V[(size_t)m0 * JDIM + i];
        float rd = fast_rcp(an);
        float wi = vi * rd;
        float wj[8];
#pragma unroll
        for (int k = 0; k < 8; k++) wj[k] = __shfl_sync(FULL, wi, 8 * h + k);
        float dw = an * wi;
#pragma unroll
        for (int k = 0; k < 4; k++) s8p[k] = pk2(dw * wj[2*k], dw * wj[2*k+1]);

        float2 y0 = *(const float2*)(y + (size_t)m0 * RDIM + 2 * h);
        zpP = pk2(y0.x, y0.y);
        fP = 0ull;
        wprevP = pk2(wi, wi);
        llogd = 0.f;

        if (m0 == s) {   // chunk 0: store row 0
            if (h == 0) g_W[(size_t)m0 * JDIM + i] = wi;
            if (i == 0) *(float2*)(g_z + (size_t)m0 * RDIM + 2 * h) =
                            make_float2(y0.x * rd, y0.y * rd);
            llogd = __logf(an);
        }
    }

    if (m0 + 1 >= e) { if (lane == 0) g_logd[warp] = llogd; return; }

    // ---- load pointers at row m0+1 (P uses row n-1)
    const float* pP8 = P + (size_t)m0 * JDIM + 8 * h;
    const float* pPi = P + (size_t)m0 * JDIM + i;
    const float* pU8 = U + (size_t)(m0 + 1) * JDIM + 8 * h;
    const float* pUi = U + (size_t)(m0 + 1) * JDIM + i;
    const float* pVi = V + (size_t)(m0 + 1) * JDIM + i;
    const float* pa1 = a + (m0 + 1);
    const float* py2 = y + (size_t)(m0 + 1) * RDIM + 2 * h;

    int sm = (m0 + 1 > s) ? (m0 + 1) : s;   // first stored row
    float* pgW = g_W + (size_t)sm * JDIM + i;
    float* pgz = g_z + (size_t)sm * RDIM + 2 * h;

    // preload row m0+1
    ulonglong2 npj  = *(const ulonglong2*)(pP8);
    ulonglong2 npjB = *(const ulonglong2*)(pP8 + 4);
    float      npi  = *pPi;
    ulonglong2 nuj  = *(const ulonglong2*)(pU8);
    ulonglong2 nujB = *(const ulonglong2*)(pU8 + 4);
    float      nui  = *pUi;
    float      nvi  = *pVi;
    float      nan  = *pa1;
    float2     ny2  = *(const float2*)(py2);

    // ---- warm phase: rows [m0+1, s) — no stores/log (empty for chunk 0)
#pragma unroll 1
    for (int n = m0 + 1; n < s; n++) FWD_STEP(false, true)

    // ---- main phase: rows [sm, e-1)
#pragma unroll 1
    for (int n = sm; n < e - 1; n++) FWD_STEP(true, true)

    // ---- peeled last row e-1: no prefetch (keeps loads in-bounds)
    FWD_STEP(true, false)

    if (lane == 0) g_logd[warp] = llogd;
}

// ---------------------------------------------------------------------------
// Kernel 2: backward solve, reverse chunked with warm-up. Distance-2
// prefetch on ALL streams.
// ---------------------------------------------------------------------------
__global__ void __launch_bounds__(256, 4)
backward_kernel(const float* __restrict__ U, const float* __restrict__ P,
                const float* __restrict__ y, float* __restrict__ xout,
                int N, int C, int L)
{
    int warp = (blockIdx.x * blockDim.x + threadIdx.x) >> 5;
    if (warp >= C) return;
    int lane = threadIdx.x & 31;
    int i = lane & 15;
    int h = lane >> 4;
    int s = warp * L;
    if (s >= N) return;
    int e = min(s + L, N);

    const unsigned FULL = 0xffffffffu;

    float g0 = 0.f, g1 = 0.f;
    float acc0 = 0.f, acc1 = 0.f;

    if (e == N) {   // last chunk: x[N-1] = z[N-1]
        float2 z2 = *(const float2*)(g_z + (size_t)(N - 1) * RDIM + 2 * h);
        float2 yv = *(const float2*)(y + (size_t)(N - 1) * RDIM + 2 * h);
        if (i == 0) *(float2*)(xout + (size_t)(N - 1) * RDIM + 2 * h) = z2;
        acc0 = yv.x * z2.x;
        acc1 = yv.y * z2.y;
    }

    int n_start = min(e - 1 + OV, N - 2);
    if (n_start < s) {
        if (i == 0) { g_yx[warp*RDIM+2*h] = acc0; g_yx[warp*RDIM+2*h+1] = acc1; }
        return;
    }

    float piA, u1A, wiA; float2 z1A, znA, yvA;
    float piB, u1B, wiB; float2 z1B, znB, yvB;
    {
        int rA = n_start;
        piA = P[(size_t)rA * JDIM + i];
        u1A = U[(size_t)(rA + 1) * JDIM + i];
        z1A = *(const float2*)(g_z + (size_t)(rA + 1) * RDIM + 2 * h);
        wiA = g_W[(size_t)rA * JDIM + i];
        znA = *(const float2*)(g_z + (size_t)rA * RDIM + 2 * h);
        yvA = *(const float2*)(y + (size_t)rA * RDIM + 2 * h);
        int rB = (n_start - 1 > s) ? n_start - 1 : s;
        piB = P[(size_t)rB * JDIM + i];
        u1B = U[(size_t)(rB + 1) * JDIM + i];
        z1B = *(const float2*)(g_z + (size_t)(rB + 1) * RDIM + 2 * h);
        wiB = g_W[(size_t)rB * JDIM + i];
        znB = *(const float2*)(g_z + (size_t)rB * RDIM + 2 * h);
        yvB = *(const float2*)(y + (size_t)rB * RDIM + 2 * h);
    }

    int pn = (n_start - 2 > s) ? n_start - 2 : s;
    const float* pPp = P + (size_t)pn * JDIM + i;
    const float* pUp = U + (size_t)(pn + 1) * JDIM + i;
    const float* pzp = g_z + (size_t)(pn + 1) * RDIM + 2 * h;
    const float* pWp = g_W + (size_t)pn * JDIM + i;
    const float* pzb = g_z + (size_t)pn * RDIM + 2 * h;
    const float* pyp = y + (size_t)pn * RDIM + 2 * h;

#pragma unroll 1
    for (int n = n_start; n >= s; n--) {
        float pi = piA, u1 = u1A, wi = wiA;
        float2 z1 = z1A, zn = znA, yv = yvA;
        piA = piB; u1A = u1B; z1A = z1B; wiA = wiB; znA = znB; yvA = yvB;
        piB = *pPp; u1B = *pUp; z1B = *(const float2*)pzp;
        wiB = *pWp; znB = *(const float2*)pzb; yvB = *(const float2*)pyp;
        int dec = (pn > s) ? JDIM : 0;
        pn -= (dec >> 4);
        pPp -= dec; pUp -= dec; pWp -= dec;
        pzp -= (dec >> 2); pzb -= (dec >> 2); pyp -= (dec >> 2);

        g0 = pi * (g0 + u1 * z1.x);
        g1 = pi * (g1 + u1 * z1.y);
        if (n < e) {   // warp-uniform branch
            float t0 = wi * g0, t1 = wi * g1;
            t0 += __shfl_xor_sync(FULL, t0, 1);  t1 += __shfl_xor_sync(FULL, t1, 1);
            t0 += __shfl_xor_sync(FULL, t0, 2);  t1 += __shfl_xor_sync(FULL, t1, 2);
            t0 += __shfl_xor_sync(FULL, t0, 4);  t1 += __shfl_xor_sync(FULL, t1, 4);
            t0 += __shfl_xor_sync(FULL, t0, 8);  t1 += __shfl_xor_sync(FULL, t1, 8);
            float x0 = zn.x - t0;
            float x1 = zn.y - t1;
            if (i == 0) *(float2*)(xout + (size_t)n * RDIM + 2 * h) =
                            make_float2(x0, x1);
            acc0 = fmaf(yv.x, x0, acc0);
            acc1 = fmaf(yv.y, x1, acc1);
        }
    }

    if (i == 0) {
        g_yx[warp * RDIM + 2 * h + 0] = acc0;
        g_yx[warp * RDIM + 2 * h + 1] = acc1;
    }
}

// ---------------------------------------------------------------------------
// Kernel 3: finalize loglike (parallel, deterministic).
// ---------------------------------------------------------------------------
__global__ void finalize_kernel(float* __restrict__ out, int N, int Cf, int Cb)
{
    const unsigned FULL = 0xffffffffu;
    int wq = threadIdx.x >> 5;
    int lane = threadIdx.x & 31;

    double sl = 0.0;
    for (int c = lane; c < Cf; c += 32) sl += (double)g_logd[c];
#pragma unroll
    for (int o = 16; o > 0; o >>= 1) sl += __shfl_xor_sync(FULL, sl, o);
    double norm = -0.5 * (sl + (double)N * log(6.283185307179586));

    double syx = 0.0;
    for (int c = lane; c < Cb; c += 32) syx += (double)g_yx[c * RDIM + wq];
#pragma unroll
    for (int o = 16; o > 0; o >>= 1) syx += __shfl_xor_sync(FULL, syx, o);

    if (lane == 0 && wq < RDIM)
        out[(size_t)N * RDIM + wq] = (float)(norm - 0.5 * syx);
}

// ---------------------------------------------------------------------------
extern "C" void kernel_launch(void* const* d_in, const int* in_sizes, int n_in,
                              void* d_out, int out_size)
{
    const float* a = (const float*)d_in[0];
    const float* U = (const float*)d_in[1];
    const float* V = (const float*)d_in[2];
    const float* P = (const float*)d_in[3];
    const float* y = (const float*)d_in[4];
    float* out = (float*)d_out;

    int N = in_sizes[0];

    // forward: 148 SMs x 24 warps = 3552 chunks
    int tf = 3552;
    int Lf = (N + tf - 1) / tf; if (Lf < 1) Lf = 1;
    int Cf = (N + Lf - 1) / Lf;
    if (Cf > MAXC) { Lf = (N + MAXC - 1) / MAXC; Cf = (N + Lf - 1) / Lf; }

    // backward: 148 SMs x 32 warps = 4736 chunks
    int tb = 4736;
    int Lb = (N + tb - 1) / tb; if (Lb < 1) Lb = 1;
    int Cb = (N + Lb - 1) / Lb;
    if (Cb > MAXC) { Lb = (N + MAXC - 1) / MAXC; Cb = (N + Lb - 1) / Lb; }

    int threads = 256;
    int blocksF = (Cf * 32 + threads - 1) / threads;
    int blocksB = (Cb * 32 + threads - 1) / threads;

    factor_forward_kernel<<<blocksF, threads>>>(a, U, V, P, y, N, Cf, Lf);
    backward_kernel<<<blocksB, threads>>>(U, P, y, out, N, Cb, Lb);
    finalize_kernel<<<1, 128>>>(out, N, Cf, Cb);
}

// round 11
// speedup vs baseline: 1.1050x; 1.0699x over previous
#include <cuda_runtime.h>
#include <cstdint>

// celerite GP factor + solve + loglike. N=262144, J=16, R=4.
// Lane-split layout: 16 lanes per chunk, TWO chunks per warp (lane halves),
// every warp instruction covers 2 sequence rows. Lane i holds the full
// S row i (8 packed f32x2 regs) and F[i][0..4). OV warm-up as before.

#define JDIM 16
#define RDIM 4
#define OV   10
#define NMAX 262144
#define MAXC 16384
#define FULLM 0xffffffffu

typedef unsigned long long u64t;

__device__ float g_W[(size_t)NMAX * JDIM];
__device__ float g_z[(size_t)NMAX * RDIM];
__device__ float g_logd[MAXC];
__device__ float g_yx[MAXC * RDIM];

__device__ __forceinline__ float fast_rcp(float x) {
    float r;
    asm("rcp.approx.f32 %0, %1;" : "=f"(r) : "f"(x));
    r = r * (2.0f - x * r);
    return r;
}
__device__ __forceinline__ u64t pk2(float lo, float hi) {
    u64t r; asm("mov.b64 %0, {%1,%2};" : "=l"(r) : "f"(lo), "f"(hi)); return r;
}
__device__ __forceinline__ void upk2(u64t v, float& lo, float& hi) {
    asm("mov.b64 {%0,%1}, %2;" : "=f"(lo), "=f"(hi) : "l"(v));
}
__device__ __forceinline__ u64t mul2(u64t a, u64t b) {
    u64t r; asm("mul.rn.f32x2 %0, %1, %2;" : "=l"(r) : "l"(a), "l"(b)); return r;
}
__device__ __forceinline__ u64t add2(u64t a, u64t b) {
    u64t r; asm("add.rn.f32x2 %0, %1, %2;" : "=l"(r) : "l"(a), "l"(b)); return r;
}
__device__ __forceinline__ u64t fma2(u64t a, u64t b, u64t c) {
    u64t r; asm("fma.rn.f32x2 %0, %1, %2, %3;" : "=l"(r) : "l"(a), "l"(b), "l"(c)); return r;
}

// ---------------------------------------------------------------------------
// Kernel 1: fused factorization + forward solve. 2 chunks/warp (lane halves).
// ---------------------------------------------------------------------------
__global__ void __launch_bounds__(256, 3)
factor_forward_kernel(const float* __restrict__ a, const float* __restrict__ U,
                      const float* __restrict__ V, const float* __restrict__ P,
                      const float* __restrict__ y, int N, int C, int L)
{
    int warp = (blockIdx.x * blockDim.x + threadIdx.x) >> 5;
    int lane = threadIdx.x & 31;
    int il  = lane & 15;
    int b16 = lane & 16;
    int half = lane >> 4;

    int chunk = 2 * warp + half;
    bool active = (chunk < C) && ((size_t)chunk * L < (size_t)N);
    int s = active ? chunk * L : 0;
    int e = min(s + L, N);
    int m0 = max(0, s - OV);
    int len = active ? (e - m0 - 1) : 0;
    int T = max(len, __shfl_xor_sync(FULLM, len, 16));

    // ---- init at row m0
    u64t S8[8];
    u64t fA, fB, zpA, zpB, wprevP;
    float llogd = 0.f;
    {
        float an = a[m0];
        float vi = V[(size_t)m0 * JDIM + il];
        float rd = fast_rcp(an);
        float wi = vi * rd;
        float wj[16];
#pragma unroll
        for (int j = 0; j < 16; j++) wj[j] = __shfl_sync(FULLM, wi, b16 + j);
        float dw = an * wi;
#pragma unroll
        for (int k = 0; k < 8; k++) S8[k] = pk2(dw * wj[2*k], dw * wj[2*k+1]);

        float4 y0 = *(const float4*)(y + (size_t)m0 * RDIM);
        zpA = pk2(y0.x, y0.y);
        zpB = pk2(y0.z, y0.w);
        fA = 0ull; fB = 0ull;
        wprevP = pk2(wi, wi);

        if (active && m0 == s) {   // chunk 0: store row 0
            g_W[(size_t)m0 * JDIM + il] = wi;
            if (il == 0) *(float4*)(g_z + (size_t)m0 * RDIM) =
                make_float4(y0.x * rd, y0.y * rd, y0.z * rd, y0.w * rd);
            llogd = __logf(an);
        }
    }

    // ---- pointers at first loop row n = m0+1 (P uses row n-1)
    int r1 = m0 + 1;
    const float* pP  = P + (size_t)m0 * JDIM;           // row n-1 (full row)
    const float* pPi = pP + il;                          // scalar P[n-1][il]
    const float* pU  = U + (size_t)r1 * JDIM;
    const float* pUi = pU + il;
    const float* pVi = V + (size_t)r1 * JDIM + il;
    const float* pa  = a + r1;
    const float* pY  = y + (size_t)r1 * RDIM;
    float* pgW = g_W + (size_t)r1 * JDIM + il;
    float* pgz = g_z + (size_t)r1 * RDIM;
    int nrow = r1;

#pragma unroll 1
    for (int t = 0; t < T; t++) {
        // loads (full rows broadcast within half; scalars per lane)
        ulonglong2 pjA = *(const ulonglong2*)(pP);
        ulonglong2 pjB = *(const ulonglong2*)(pP + 4);
        ulonglong2 pjC = *(const ulonglong2*)(pP + 8);
        ulonglong2 pjD = *(const ulonglong2*)(pP + 12);
        float pi = *pPi;
        ulonglong2 ujA = *(const ulonglong2*)(pU);
        ulonglong2 ujB = *(const ulonglong2*)(pU + 4);
        ulonglong2 ujC = *(const ulonglong2*)(pU + 8);
        ulonglong2 ujD = *(const ulonglong2*)(pU + 12);
        float ui = *pUi;
        float vi = *pVi;
        float an = *pa;
        float4 yv = *(const float4*)(pY);

        u64t pis = pk2(pi, pi);

        // F recurrence
        fA = mul2(pis, fma2(wprevP, zpA, fA));
        fB = mul2(pis, fma2(wprevP, zpB, fB));

        // S decay (row i scaled by pi * pj elementwise)
        S8[0] = mul2(S8[0], mul2(pis, pjA.x));
        S8[1] = mul2(S8[1], mul2(pis, pjA.y));
        S8[2] = mul2(S8[2], mul2(pis, pjB.x));
        S8[3] = mul2(S8[3], mul2(pis, pjB.y));
        S8[4] = mul2(S8[4], mul2(pis, pjC.x));
        S8[5] = mul2(S8[5], mul2(pis, pjC.y));
        S8[6] = mul2(S8[6], mul2(pis, pjD.x));
        S8[7] = mul2(S8[7], mul2(pis, pjD.y));

        // su_i = S row . U row  (fully lane-local)
        u64t q0 = mul2(S8[0], ujA.x), q1 = mul2(S8[1], ujA.y);
        u64t q2 = mul2(S8[2], ujB.x), q3 = mul2(S8[3], ujB.y);
        u64t q4 = mul2(S8[4], ujC.x), q5 = mul2(S8[5], ujC.y);
        u64t q6 = mul2(S8[6], ujD.x), q7 = mul2(S8[7], ujD.y);
        u64t qa = add2(add2(q0, q1), add2(q2, q3));
        u64t qb = add2(add2(q4, q5), add2(q6, q7));
        u64t qt = add2(qa, qb);
        float qlo, qhi; upk2(qt, qlo, qhi);
        float su = qlo + qhi;

        // reductions over the 16-lane half: tD = U.SU, t0..t3 = U.F
        float fl0, fl1, fl2, fl3;
        upk2(fA, fl0, fl1); upk2(fB, fl2, fl3);
        float tD = ui * su;
        float t0 = ui * fl0, t1 = ui * fl1, t2 = ui * fl2, t3 = ui * fl3;
#pragma unroll
        for (int o = 1; o <= 8; o <<= 1) {
            tD += __shfl_xor_sync(FULLM, tD, o);
            t0 += __shfl_xor_sync(FULLM, t0, o);
            t1 += __shfl_xor_sync(FULLM, t1, o);
            t2 += __shfl_xor_sync(FULLM, t2, o);
            t3 += __shfl_xor_sync(FULLM, t3, o);
        }

        float dn = an - tD;
        float rd = fast_rcp(dn);
        float wi = (vi - su) * rd;
        float zn0 = yv.x - t0, zn1 = yv.y - t1;
        float zn2 = yv.z - t2, zn3 = yv.w - t3;

        bool pr = (t < len) && (nrow >= s);
        if (pr) *pgW = wi;
        if (pr && il == 0)
            *(float4*)pgz = make_float4(zn0 * rd, zn1 * rd, zn2 * rd, zn3 * rd);
        llogd += pr ? __logf(dn) : 0.f;

        // rank-1 update: S += dn * w w^T
        float wj[16];
#pragma unroll
        for (int j = 0; j < 16; j++) wj[j] = __shfl_sync(FULLM, wi, b16 + j);
        float dwv = dn * wi;
        u64t dwP = pk2(dwv, dwv);
#pragma unroll
        for (int k = 0; k < 8; k++)
            S8[k] = fma2(dwP, pk2(wj[2*k], wj[2*k+1]), S8[k]);

        wprevP = pk2(wi, wi);
        zpA = pk2(zn0, zn1);
        zpB = pk2(zn2, zn3);

        // predicated pointer advance (freeze on tail)
        bool adv = (t + 1 < len);
        int d16 = adv ? JDIM : 0;
        int d4  = adv ? RDIM : 0;
        int d1  = adv ? 1 : 0;
        pP += d16; pPi += d16; pU += d16; pUi += d16; pVi += d16;
        pa += d1; pY += d4; pgW += d16; pgz += d4; nrow += d1;
    }

    if (active && il == 0) g_logd[chunk] = llogd;
}

// ---------------------------------------------------------------------------
// Kernel 2: backward solve. 2 chunks/warp (lane halves). Lane i holds G[i][0..4).
// ---------------------------------------------------------------------------
__global__ void __launch_bounds__(256, 4)
backward_kernel(const float* __restrict__ U, const float* __restrict__ P,
                const float* __restrict__ y, float* __restrict__ xout,
                int N, int C, int L)
{
    int warp = (blockIdx.x * blockDim.x + threadIdx.x) >> 5;
    int lane = threadIdx.x & 31;
    int il  = lane & 15;
    int half = lane >> 4;

    int chunk = 2 * warp + half;
    bool active = (chunk < C) && ((size_t)chunk * L < (size_t)N);
    int s = active ? chunk * L : 0;
    int e = min(s + L, N);

    float g0 = 0.f, g1 = 0.f, g2 = 0.f, g3 = 0.f;
    float acc0 = 0.f, acc1 = 0.f, acc2 = 0.f, acc3 = 0.f;

    if (active && e == N) {   // last chunk: x[N-1] = z[N-1]
        float4 z2 = *(const float4*)(g_z + (size_t)(N - 1) * RDIM);
        float4 yv = *(const float4*)(y + (size_t)(N - 1) * RDIM);
        if (il == 0) *(float4*)(xout + (size_t)(N - 1) * RDIM) = z2;
        acc0 = yv.x * z2.x; acc1 = yv.y * z2.y;
        acc2 = yv.z * z2.z; acc3 = yv.w * z2.w;
    }

    int n_start = min(e - 1 + OV, N - 2);
    int len = active ? max(0, n_start - s + 1) : 0;
    int T = max(len, __shfl_xor_sync(FULLM, len, 16));

    int row = (len > 0) ? n_start : 0;
    const float* pPi = P + (size_t)row * JDIM + il;
    const float* pUi = U + (size_t)(row + 1) * JDIM + il;
    const float* pz1 = g_z + (size_t)(row + 1) * RDIM;
    const float* pW  = g_W + (size_t)row * JDIM + il;
    const float* pzn = g_z + (size_t)row * RDIM;
    const float* pY  = y + (size_t)row * RDIM;
    float*       pX  = xout + (size_t)row * RDIM;
    int nrow = row;

#pragma unroll 1
    for (int t = 0; t < T; t++) {
        float pi = *pPi;
        float u1 = *pUi;
        float4 z1 = *(const float4*)pz1;
        g0 = pi * (g0 + u1 * z1.x);
        g1 = pi * (g1 + u1 * z1.y);
        g2 = pi * (g2 + u1 * z1.z);
        g3 = pi * (g3 + u1 * z1.w);

        float wi = *pW;
        float t0 = wi * g0, t1 = wi * g1, t2 = wi * g2, t3 = wi * g3;
#pragma unroll
        for (int o = 1; o <= 8; o <<= 1) {
            t0 += __shfl_xor_sync(FULLM, t0, o);
            t1 += __shfl_xor_sync(FULLM, t1, o);
            t2 += __shfl_xor_sync(FULLM, t2, o);
            t3 += __shfl_xor_sync(FULLM, t3, o);
        }

        float4 zn = *(const float4*)pzn;
        float x0 = zn.x - t0, x1 = zn.y - t1;
        float x2 = zn.z - t2, x3 = zn.w - t3;

        bool pr = (t < len) && (nrow < e);
        if (pr && il == 0) *(float4*)pX = make_float4(x0, x1, x2, x3);
        float4 yv = *(const float4*)pY;
        acc0 += pr ? yv.x * x0 : 0.f;
        acc1 += pr ? yv.y * x1 : 0.f;
        acc2 += pr ? yv.z * x2 : 0.f;
        acc3 += pr ? yv.w * x3 : 0.f;

        bool adv = (t + 1 < len);
        int d16 = adv ? JDIM : 0;
        int d4  = adv ? RDIM : 0;
        pPi -= d16; pUi -= d16; pW -= d16;
        pz1 -= d4; pzn -= d4; pY -= d4; pX -= d4;
        nrow -= adv ? 1 : 0;
    }

    if (active && il == 0)
        *(float4*)(g_yx + (size_t)chunk * RDIM) = make_float4(acc0, acc1, acc2, acc3);
}

// ---------------------------------------------------------------------------
// Kernel 3: finalize loglike (parallel, deterministic).
// ---------------------------------------------------------------------------
__global__ void finalize_kernel(float* __restrict__ out, int N, int Cf, int Cb)
{
    int wq = threadIdx.x >> 5;
    int lane = threadIdx.x & 31;

    double sl = 0.0;
    for (int c = lane; c < Cf; c += 32) sl += (double)g_logd[c];
#pragma unroll
    for (int o = 16; o > 0; o >>= 1) sl += __shfl_xor_sync(FULLM, sl, o);
    double norm = -0.5 * (sl + (double)N * log(6.283185307179586));

    double syx = 0.0;
    for (int c = lane; c < Cb; c += 32) syx += (double)g_yx[c * RDIM + wq];
#pragma unroll
    for (int o = 16; o > 0; o >>= 1) syx += __shfl_xor_sync(FULLM, syx, o);

    if (lane == 0 && wq < RDIM)
        out[(size_t)N * RDIM + wq] = (float)(norm - 0.5 * syx);
}

// ---------------------------------------------------------------------------
extern "C" void kernel_launch(void* const* d_in, const int* in_sizes, int n_in,
                              void* d_out, int out_size)
{
    const float* a = (const float*)d_in[0];
    const float* U = (const float*)d_in[1];
    const float* V = (const float*)d_in[2];
    const float* P = (const float*)d_in[3];
    const float* y = (const float*)d_in[4];
    float* out = (float*)d_out;

    int N = in_sizes[0];

    // forward: ~3552 warps x 2 chunks = ~7104 chunks (24 warps/SM)
    int ctF = 7104;
    int Lf = (N + ctF - 1) / ctF; if (Lf < 1) Lf = 1;
    int Cf = (N + Lf - 1) / Lf;
    if (Cf > MAXC) { Lf = (N + MAXC - 1) / MAXC; Cf = (N + Lf - 1) / Lf; }
    int warpsF = (Cf + 1) / 2;
    int blocksF = (warpsF * 32 + 255) / 256;

    // backward: ~4736 warps x 2 chunks = ~9472 chunks (32 warps/SM)
    int ctB = 9472;
    int Lb = (N + ctB - 1) / ctB; if (Lb < 1) Lb = 1;
    int Cb = (N + Lb - 1) / Lb;
    if (Cb > MAXC) { Lb = (N + MAXC - 1) / MAXC; Cb = (N + Lb - 1) / Lb; }
    int warpsB = (Cb + 1) / 2;
    int blocksB = (warpsB * 32 + 255) / 256;

    factor_forward_kernel<<<blocksF, 256>>>(a, U, V, P, y, N, Cf, Lf);
    backward_kernel<<<blocksB, 256>>>(U, P, y, out, N, Cb, Lb);
    finalize_kernel<<<1, 128>>>(out, N, Cf, Cb);
}